// round 10
// baseline (speedup 1.0000x reference)
#include <cuda_runtime.h>
#include <cuda_bf16.h>
#include <cstdint>
#include <cstddef>

#define BATCH 256
#define SEQ 145
#define DM 388
#define DI 776
#define DS 16
#define DC 4
#define DR 25
#define NB 5
#define TOK (BATCH*SEQ)          /* 37120 */
#define XPO (DR + 2*DS)          /* 57 */
#define FLAT (SEQ*DM)            /* 56260 */

// tight split-K3 per GEMM (3*K rounded up to 64)
#define K3_IN  1216              /* 3*388=1164 -> 1216 */
#define K3_XP  2368              /* 3*776=2328 -> 2368 */
#define K3_DT  128               /* 3*25=75   -> 128  */
#define K3_OUT 2368
#define NP_IN  1664
#define NP_XP  128
#define NP_DT  896
#define NP_OUT 512
#define PAD_XP (K3_XP - 3*DI)    /* 40 */
#define PAD_IN (K3_IN - 3*DM)    /* 52 */

// ---------------- scratch ----------------
__device__ float g_xz [TOK*2*DI];
__device__ float g_xc [TOK*DI];
__device__ float g_dbl[TOK*XPO];
__device__ float g_dt [TOK*DI];
__device__ float g_x  [TOK*DM];
__device__ __nv_bfloat16 g_a3[(size_t)TOK*K3_XP];       // split activations (max row 2368)
__device__ __nv_bfloat16 g_b3[(size_t)NP_IN*K3_IN];     // split weights (max 1664*1216)

// ---------------- helpers ----------------
__device__ __forceinline__ uint32_t smem_u32(const void* p) {
    uint32_t a;
    asm("{ .reg .u64 t; cvta.to.shared.u64 t, %1; cvt.u32.u64 %0, t; }" : "=r"(a) : "l"(p));
    return a;
}
__device__ __forceinline__ void cpasync16(uint32_t s, const void* g) {
    asm volatile("cp.async.cg.shared.global [%0], [%1], 16;" :: "r"(s), "l"(g));
}
__device__ __forceinline__ void ldsm4(uint32_t* r, uint32_t a) {
    asm volatile("ldmatrix.sync.aligned.m8n8.x4.shared.b16 {%0,%1,%2,%3}, [%4];"
                 : "=r"(r[0]), "=r"(r[1]), "=r"(r[2]), "=r"(r[3]) : "r"(a));
}
__device__ __forceinline__ void ldsm2(uint32_t* r, uint32_t a) {
    asm volatile("ldmatrix.sync.aligned.m8n8.x2.shared.b16 {%0,%1}, [%2];"
                 : "=r"(r[0]), "=r"(r[1]) : "r"(a));
}
__device__ __forceinline__ void mma16816(float* d, const uint32_t* a, const uint32_t* b) {
    asm volatile("mma.sync.aligned.m16n8k16.row.col.f32.bf16.bf16.f32 "
                 "{%0,%1,%2,%3}, {%4,%5,%6,%7}, {%8,%9}, {%0,%1,%2,%3};"
                 : "+f"(d[0]), "+f"(d[1]), "+f"(d[2]), "+f"(d[3])
                 : "r"(a[0]), "r"(a[1]), "r"(a[2]), "r"(a[3]), "r"(b[0]), "r"(b[1]));
}
__device__ __forceinline__ void split_bf16(float v, __nv_bfloat16& h, __nv_bfloat16& l) {
    h = __float2bfloat16(v);
    l = __float2bfloat16(v - __bfloat162float(h));
}

// ---------------- bf16 HMMA GEMM (3-stage cp.async pipeline, 2 CTA/SM) ----------------
// C[M,N] = A3[M,K3] x B3[Np,K3]^T, fp32 accum. M%128==0, Np%128==0, K3%64==0.
__global__ void __launch_bounds__(256, 2)
mma_gemm(const __nv_bfloat16* __restrict__ A, const __nv_bfloat16* __restrict__ B, int K3,
         float* __restrict__ C, int sC, int N,
         const float* __restrict__ bias, int act) {
    extern __shared__ char smem[];
    uint32_t sb = smem_u32(smem);
    const uint32_t SAo[3] = {0, 32768, 65536};
    const uint32_t SBo[3] = {16384, 49152, 81920};
    int tid = threadIdx.x, wid = tid >> 5, lane = tid & 31;
    int wm = wid & 1, wn = wid >> 1;          // 2 x 4 warp grid
    int m0 = blockIdx.x * 128, n0 = blockIdx.y * 128;

    int lrow[4], lc[4];
    uint32_t lso[4];
    #pragma unroll
    for (int j = 0; j < 4; j++) {
        int cid = tid + j * 256;
        lrow[j] = cid >> 3;
        lc[j] = cid & 7;
        lso[j] = (uint32_t)(lrow[j] * 128 + ((lc[j] ^ (lrow[j] & 7)) * 16));
    }

    auto prefetch = [&](int k0, int st) {
        #pragma unroll
        for (int j = 0; j < 4; j++) {
            const __nv_bfloat16* ga = A + (size_t)(m0 + lrow[j]) * K3 + k0 + lc[j] * 8;
            const __nv_bfloat16* gb = B + (size_t)(n0 + lrow[j]) * K3 + k0 + lc[j] * 8;
            cpasync16(sb + SAo[st] + lso[j], ga);
            cpasync16(sb + SBo[st] + lso[j], gb);
        }
        asm volatile("cp.async.commit_group;" ::: "memory");
    };

    float acc[4][4][4];
    #pragma unroll
    for (int i = 0; i < 4; i++)
        #pragma unroll
        for (int j = 0; j < 4; j++)
            #pragma unroll
            for (int r = 0; r < 4; r++) acc[i][j][r] = 0.f;

    int rowA[4], rowB[4];
    #pragma unroll
    for (int mi = 0; mi < 4; mi++) rowA[mi] = wm * 64 + mi * 16 + (lane & 15);
    #pragma unroll
    for (int nj = 0; nj < 4; nj++) rowB[nj] = wn * 32 + nj * 8 + (lane & 7);
    int hiA = lane >> 4;
    int hiB = (lane >> 3) & 1;

    int nk = K3 >> 6;
    prefetch(0, 0);
    prefetch(64, 1);

    for (int t = 0; t < nk; t++) {
        asm volatile("cp.async.wait_group 1;" ::: "memory");
        __syncthreads();
        if (t + 2 < nk) prefetch((t + 2) * 64, (t + 2) % 3);
        else asm volatile("cp.async.commit_group;" ::: "memory");
        int cur = t % 3;
        #pragma unroll
        for (int ks = 0; ks < 4; ks++) {
            uint32_t af[4][4], bf[4][2];
            #pragma unroll
            for (int mi = 0; mi < 4; mi++) {
                uint32_t off = (uint32_t)(rowA[mi] * 128 + (((2 * ks + hiA) ^ (rowA[mi] & 7)) * 16));
                ldsm4(af[mi], sb + SAo[cur] + off);
            }
            #pragma unroll
            for (int nj = 0; nj < 4; nj++) {
                uint32_t off = (uint32_t)(rowB[nj] * 128 + (((2 * ks + hiB) ^ (rowB[nj] & 7)) * 16));
                ldsm2(bf[nj], sb + SBo[cur] + off);
            }
            #pragma unroll
            for (int mi = 0; mi < 4; mi++)
                #pragma unroll
                for (int nj = 0; nj < 4; nj++)
                    mma16816(acc[mi][nj], af[mi], bf[nj]);
        }
    }
    __syncthreads();

    int rbase = m0 + wm * 64 + (lane >> 2);
    int cbase = n0 + wn * 32 + 2 * (lane & 3);
    #pragma unroll
    for (int mi = 0; mi < 4; mi++) {
        #pragma unroll
        for (int rh = 0; rh < 2; rh++) {
            int row = rbase + mi * 16 + rh * 8;
            float* crow = C + (size_t)row * sC;
            #pragma unroll
            for (int nj = 0; nj < 4; nj++) {
                #pragma unroll
                for (int cl = 0; cl < 2; cl++) {
                    int col = cbase + nj * 8 + cl;
                    if (col < N) {
                        float v = acc[mi][nj][rh * 2 + cl];
                        if (bias) v += bias[col];
                        if (act == 1) v = fmaxf(v, 0.f) + log1pf(__expf(-fabsf(v)));
                        crow[col] = v;
                    }
                }
            }
        }
    }
}

// ---------------- weights: fp32 -> tight [Bh(K)|Bl(K)|Bh(K)|0] ----------------
__global__ void cvt_w3(const float* __restrict__ W, int N, int K, int Np, int K3,
                       __nv_bfloat16* __restrict__ dst) {
    int idx = blockIdx.x * blockDim.x + threadIdx.x;
    if (idx >= Np * K3) return;
    int j = idx % K3, n = idx / K3;
    float out = 0.f;
    if (n < N) {
        if (j < K) {
            float v = W[(size_t)n * K + j];
            out = __bfloat162float(__float2bfloat16(v));     // hi
        } else if (j < 2 * K) {
            float v = W[(size_t)n * K + (j - K)];
            __nv_bfloat16 h, l; split_bf16(v, h, l);
            dst[idx] = l; return;                            // lo
        } else if (j < 3 * K) {
            float v = W[(size_t)n * K + (j - 2 * K)];
            out = __bfloat162float(__float2bfloat16(v));     // hi
        }
    }
    dst[idx] = __float2bfloat16(out);
}

// ---------------- dt slice: dbl[:, :25] -> tight [Ah|Ah|Al|0] K3=128 ----------------
__global__ void cvt_dt(const float* __restrict__ dbl, __nv_bfloat16* __restrict__ dst) {
    int idx = blockIdx.x * blockDim.x + threadIdx.x;
    if (idx >= TOK * K3_DT) return;
    int j = idx % K3_DT, r = idx / K3_DT;
    __nv_bfloat16 o = __float2bfloat16(0.f);
    if (j < 2 * DR) {
        int k = (j < DR) ? j : j - DR;
        o = __float2bfloat16(dbl[(size_t)r * XPO + k]);
    } else if (j < 3 * DR) {
        float v = dbl[(size_t)r * XPO + (j - 2 * DR)];
        __nv_bfloat16 h, l; split_bf16(v, h, l);
        o = l;
    }
    dst[idx] = o;
}

// ---------------- layernorm fused with tight split (K3_IN) ----------------
__global__ void ln_split(const float* __restrict__ x, const float* __restrict__ g,
                         const float* __restrict__ beta, __nv_bfloat16* __restrict__ a3) {
    int t = blockIdx.x;
    const float* xr = x + (size_t)t * DM;
    float s = 0.f, s2 = 0.f;
    for (int i = threadIdx.x; i < DM; i += 128) {
        float v = xr[i]; s += v; s2 += v * v;
    }
    #pragma unroll
    for (int o = 16; o; o >>= 1) {
        s  += __shfl_down_sync(0xffffffffu, s,  o);
        s2 += __shfl_down_sync(0xffffffffu, s2, o);
    }
    __shared__ float sh[2][4];
    __shared__ float mu_s, rs_s;
    int w = threadIdx.x >> 5, ln = threadIdx.x & 31;
    if (ln == 0) { sh[0][w] = s; sh[1][w] = s2; }
    __syncthreads();
    if (threadIdx.x == 0) {
        float S  = sh[0][0] + sh[0][1] + sh[0][2] + sh[0][3];
        float S2 = sh[1][0] + sh[1][1] + sh[1][2] + sh[1][3];
        float mu = S / DM;
        float var = S2 / DM - mu * mu;
        mu_s = mu;
        rs_s = rsqrtf(var + 1e-5f);
    }
    __syncthreads();
    float mu = mu_s, rs = rs_s;
    __nv_bfloat16* row = a3 + (size_t)t * K3_IN;
    for (int i = threadIdx.x; i < DM; i += 128) {
        float v = (xr[i] - mu) * rs * g[i] + beta[i];
        __nv_bfloat16 h, l;
        split_bf16(v, h, l);
        row[i] = h;
        row[DM + i] = h;
        row[2 * DM + i] = l;
    }
    for (int i = 3 * DM + threadIdx.x; i < K3_IN; i += 128)
        row[i] = __float2bfloat16(0.f);
}

// ---------------- conv+SiLU fused with tight split (K3_XP) ----------------
__global__ void conv_silu_split(const float* __restrict__ xz, const float* __restrict__ cw,
                                const float* __restrict__ cb, float* __restrict__ xc,
                                __nv_bfloat16* __restrict__ a3) {
    int idx = blockIdx.x * blockDim.x + threadIdx.x;
    if (idx >= TOK * (DI + PAD_XP)) return;
    int d = idx % (DI + PAD_XP);
    int r = idx / (DI + PAD_XP);
    __nv_bfloat16* row = a3 + (size_t)r * K3_XP;
    if (d >= DI) {                       // tail zero: index 2*DI + d covers [3*DI, K3_XP)
        row[2 * DI + d] = __float2bfloat16(0.f);
        return;
    }
    int l = r % SEQ;
    int b = r / SEQ;
    const float* base = xz + (size_t)(b * SEQ) * (2 * DI) + d;
    const float* w = cw + d * DC;
    float acc = cb[d];
    #pragma unroll
    for (int j = 0; j < DC; j++) {
        int ls = l - (DC - 1) + j;
        if (ls >= 0) acc += w[j] * base[(size_t)ls * (2 * DI)];
    }
    float v = acc / (1.f + __expf(-acc));
    xc[(size_t)r * DI + d] = v;
    __nv_bfloat16 h, lo;
    split_bf16(v, h, lo);
    row[d] = h; row[DI + d] = h; row[2 * DI + d] = lo;
}

// ---------------- selective scan, writes gated y as tight split (K3_XP) ----------------
__global__ void scan_split(const float* __restrict__ dt, const float* __restrict__ u,
                           const float* __restrict__ dbl, const float* __restrict__ xz,
                           const float* __restrict__ A_log, const float* __restrict__ Dp,
                           __nv_bfloat16* __restrict__ a3) {
    int idx = blockIdx.x * blockDim.x + threadIdx.x;
    if (idx >= BATCH * (DI + PAD_XP)) return;
    int d = idx % (DI + PAD_XP);
    int b = idx / (DI + PAD_XP);
    size_t tok0 = (size_t)b * SEQ;
    if (d >= DI) {
        __nv_bfloat16 z = __float2bfloat16(0.f);
        for (int l = 0; l < SEQ; l++)
            a3[(tok0 + l) * K3_XP + 2 * DI + d] = z;
        return;
    }
    float Aa[DS];
    #pragma unroll
    for (int n = 0; n < DS; n++) Aa[n] = -__expf(A_log[d * DS + n]);
    float Dv = Dp[d];
    float h[DS];
    #pragma unroll
    for (int n = 0; n < DS; n++) h[n] = 0.f;
    for (int l = 0; l < SEQ; l++) {
        size_t t = tok0 + l;
        float dtv = dt[t * DI + d];
        float uv  = u [t * DI + d];
        const float* rb = dbl + t * XPO;
        float dtu = dtv * uv;
        float yy = 0.f;
        #pragma unroll
        for (int n = 0; n < DS; n++) {
            float e = __expf(dtv * Aa[n]);
            h[n] = e * h[n] + dtu * rb[DR + n];
            yy += h[n] * rb[DR + DS + n];
        }
        float zv = xz[t * (2 * DI) + DI + d];
        yy += uv * Dv;
        float v = yy * (zv / (1.f + __expf(-zv)));
        __nv_bfloat16 hh, ll;
        split_bf16(v, hh, ll);
        __nv_bfloat16* row = a3 + t * K3_XP;
        row[d] = hh; row[DI + d] = hh; row[2 * DI + d] = ll;
    }
}

// ---------------- classifier ----------------
__global__ void cls_kernel(const float* __restrict__ x, const float* __restrict__ w,
                           const float* __restrict__ bias, float* __restrict__ out) {
    int b = blockIdx.x;
    const float* xr = x + (size_t)b * FLAT;
    float a0 = 0.f, a1 = 0.f, a2 = 0.f;
    for (int i = threadIdx.x; i < FLAT; i += 256) {
        float v = xr[i];
        a0 += v * w[i];
        a1 += v * w[FLAT + i];
        a2 += v * w[2 * FLAT + i];
    }
    #pragma unroll
    for (int o = 16; o; o >>= 1) {
        a0 += __shfl_down_sync(0xffffffffu, a0, o);
        a1 += __shfl_down_sync(0xffffffffu, a1, o);
        a2 += __shfl_down_sync(0xffffffffu, a2, o);
    }
    __shared__ float sh[3][8];
    int wi = threadIdx.x >> 5, ln = threadIdx.x & 31;
    if (ln == 0) { sh[0][wi] = a0; sh[1][wi] = a1; sh[2][wi] = a2; }
    __syncthreads();
    if (threadIdx.x == 0) {
        float l0 = bias[0], l1 = bias[1], l2 = bias[2];
        for (int k = 0; k < 8; k++) { l0 += sh[0][k]; l1 += sh[1][k]; l2 += sh[2][k]; }
        float m = fmaxf(l0, fmaxf(l1, l2));
        float e0 = expf(l0 - m), e1 = expf(l1 - m), e2 = expf(l2 - m);
        float inv = 1.f / (e0 + e1 + e2);
        out[b * 3 + 0] = e0 * inv;
        out[b * 3 + 1] = e1 * inv;
        out[b * 3 + 2] = e2 * inv;
    }
}

// ---------------- host launch ----------------
#define MMA_SMEM 98304

extern "C" void kernel_launch(void* const* d_in, const int* in_sizes, int n_in,
                              void* d_out, int out_size) {
    const float* x_in   = (const float*)d_in[0];
    const float* ln_g   = (const float*)d_in[1];
    const float* ln_b   = (const float*)d_in[2];
    const float* inp_w  = (const float*)d_in[3];
    const float* conv_w = (const float*)d_in[4];
    const float* conv_b = (const float*)d_in[5];
    const float* xp_w   = (const float*)d_in[6];
    const float* dt_w   = (const float*)d_in[7];
    const float* dt_b   = (const float*)d_in[8];
    const float* A_log  = (const float*)d_in[9];
    const float* Dp     = (const float*)d_in[10];
    const float* out_w  = (const float*)d_in[11];
    const float* cls_w  = (const float*)d_in[12];
    const float* cls_b  = (const float*)d_in[13];
    float* out = (float*)d_out;

    float *p_xz, *p_xc, *p_dbl, *p_dt, *p_x;
    __nv_bfloat16 *p_a3, *p_b3;
    cudaGetSymbolAddress((void**)&p_xz,  g_xz);
    cudaGetSymbolAddress((void**)&p_xc,  g_xc);
    cudaGetSymbolAddress((void**)&p_dbl, g_dbl);
    cudaGetSymbolAddress((void**)&p_dt,  g_dt);
    cudaGetSymbolAddress((void**)&p_x,   g_x);
    cudaGetSymbolAddress((void**)&p_a3,  g_a3);
    cudaGetSymbolAddress((void**)&p_b3,  g_b3);

    cudaFuncSetAttribute(mma_gemm, cudaFuncAttributeMaxDynamicSharedMemorySize, MMA_SMEM);

    const int MB = TOK / 128;  // 290

    for (int i = 0; i < NB; i++) {
        const float* src = (i == 0) ? x_in : p_x;
        ln_split<<<TOK, 128>>>(src, ln_g + i * DM, ln_b + i * DM, p_a3);

        // ---- in_proj
        cvt_w3<<<(NP_IN * K3_IN + 255) / 256, 256>>>(inp_w + (size_t)i * 2 * DI * DM,
                                                     2 * DI, DM, NP_IN, K3_IN, p_b3);
        mma_gemm<<<dim3(MB, NP_IN / 128), 256, MMA_SMEM>>>(p_a3, p_b3, K3_IN,
                                                           p_xz, 2 * DI, 2 * DI, nullptr, 0);

        conv_silu_split<<<(TOK * (DI + PAD_XP) + 255) / 256, 256>>>(
            p_xz, conv_w + (size_t)i * DI * DC, conv_b + (size_t)i * DI, p_xc, p_a3);

        // ---- x_proj
        cvt_w3<<<(NP_XP * K3_XP + 255) / 256, 256>>>(xp_w + (size_t)i * XPO * DI,
                                                     XPO, DI, NP_XP, K3_XP, p_b3);
        mma_gemm<<<dim3(MB, NP_XP / 128), 256, MMA_SMEM>>>(p_a3, p_b3, K3_XP,
                                                           p_dbl, XPO, XPO, nullptr, 0);

        // ---- dt_proj
        cvt_dt<<<(TOK * K3_DT + 255) / 256, 256>>>(p_dbl, p_a3);
        cvt_w3<<<(NP_DT * K3_DT + 255) / 256, 256>>>(dt_w + (size_t)i * DI * DR,
                                                     DI, DR, NP_DT, K3_DT, p_b3);
        mma_gemm<<<dim3(MB, NP_DT / 128), 256, MMA_SMEM>>>(p_a3, p_b3, K3_DT,
                                                           p_dt, DI, DI, dt_b + (size_t)i * DI, 1);

        // scan + gate + split
        scan_split<<<(BATCH * (DI + PAD_XP) + 127) / 128, 128>>>(
            p_dt, p_xc, p_dbl, p_xz,
            A_log + (size_t)i * DI * DS, Dp + (size_t)i * DI, p_a3);

        // ---- out_proj
        cvt_w3<<<(NP_OUT * K3_OUT + 255) / 256, 256>>>(out_w + (size_t)i * DM * DI,
                                                       DM, DI, NP_OUT, K3_OUT, p_b3);
        mma_gemm<<<dim3(MB, NP_OUT / 128), 256, MMA_SMEM>>>(p_a3, p_b3, K3_OUT,
                                                            p_x, DM, DM, nullptr, 0);
    }

    cls_kernel<<<BATCH, 256>>>(p_x, cls_w, cls_b, out);
}

// round 12
// speedup vs baseline: 1.4215x; 1.4215x over previous
#include <cuda_runtime.h>
#include <cuda_bf16.h>
#include <cstdint>
#include <cstddef>

#define BATCH 256
#define SEQ 145
#define DM 388
#define DI 776
#define DS 16
#define DC 4
#define DR 25
#define NB 5
#define TOK (BATCH*SEQ)          /* 37120 */
#define XPO (DR + 2*DS)          /* 57 */
#define FLAT (SEQ*DM)            /* 56260 */

// padded K (before 3x split concat) and padded N per GEMM
#define KP_IN  448
#define NP_IN  1664
#define KP_XP  832
#define NP_XP  128
#define KP_DT  64
#define NP_DT  896
#define KP_OUT 832
#define NP_OUT 512
#define MAXK3  (3*832)           /* 2496 */

// ---------------- scratch ----------------
__device__ float g_xz [TOK*2*DI];
__device__ float g_xc [TOK*DI];
__device__ float g_dbl[TOK*XPO];
__device__ float g_dt [TOK*DI];
__device__ float g_x  [TOK*DM];
__device__ __nv_bfloat16 g_a3[(size_t)TOK*MAXK3];       // split activations [TOK, 3*Kp]
__device__ __nv_bfloat16 g_b3[(size_t)NP_IN*3*KP_IN];   // split weights (max 1664*1344)

// ---------------- helpers ----------------
__device__ __forceinline__ uint32_t smem_u32(const void* p) {
    uint32_t a;
    asm("{ .reg .u64 t; cvta.to.shared.u64 t, %1; cvt.u32.u64 %0, t; }" : "=r"(a) : "l"(p));
    return a;
}
__device__ __forceinline__ void cpasync16(uint32_t s, const void* g) {
    asm volatile("cp.async.cg.shared.global [%0], [%1], 16;" :: "r"(s), "l"(g));
}
__device__ __forceinline__ void ldsm4(uint32_t* r, uint32_t a) {
    asm volatile("ldmatrix.sync.aligned.m8n8.x4.shared.b16 {%0,%1,%2,%3}, [%4];"
                 : "=r"(r[0]), "=r"(r[1]), "=r"(r[2]), "=r"(r[3]) : "r"(a));
}
__device__ __forceinline__ void ldsm2(uint32_t* r, uint32_t a) {
    asm volatile("ldmatrix.sync.aligned.m8n8.x2.shared.b16 {%0,%1}, [%2];"
                 : "=r"(r[0]), "=r"(r[1]) : "r"(a));
}
__device__ __forceinline__ void mma16816(float* d, const uint32_t* a, const uint32_t* b) {
    asm volatile("mma.sync.aligned.m16n8k16.row.col.f32.bf16.bf16.f32 "
                 "{%0,%1,%2,%3}, {%4,%5,%6,%7}, {%8,%9}, {%0,%1,%2,%3};"
                 : "+f"(d[0]), "+f"(d[1]), "+f"(d[2]), "+f"(d[3])
                 : "r"(a[0]), "r"(a[1]), "r"(a[2]), "r"(a[3]), "r"(b[0]), "r"(b[1]));
}
__device__ __forceinline__ void split_bf16(float v, __nv_bfloat16& h, __nv_bfloat16& l) {
    h = __float2bfloat16(v);
    l = __float2bfloat16(v - __bfloat162float(h));
}

// ---------------- bf16 HMMA GEMM (3-stage cp.async pipeline, 2 CTA/SM) ----------------
// C[M,N] = A3[M,K3] x B3[Np,K3]^T, fp32 accum. M%128==0, Np%128==0, K3%64==0, K3>=192.
__global__ void __launch_bounds__(256, 2)
mma_gemm(const __nv_bfloat16* __restrict__ A, const __nv_bfloat16* __restrict__ B, int K3,
         float* __restrict__ C, int sC, int N,
         const float* __restrict__ bias, int act) {
    extern __shared__ char smem[];
    uint32_t sb = smem_u32(smem);
    // per stage: A 16KB + B 16KB
    const uint32_t SAo[3] = {0, 32768, 65536};
    const uint32_t SBo[3] = {16384, 49152, 81920};
    int tid = threadIdx.x, wid = tid >> 5, lane = tid & 31;
    int wm = wid & 1, wn = wid >> 1;          // 2 x 4 warp grid
    int m0 = blockIdx.x * 128, n0 = blockIdx.y * 128;

    int lrow[4], lc[4];
    uint32_t lso[4];
    #pragma unroll
    for (int j = 0; j < 4; j++) {
        int cid = tid + j * 256;
        lrow[j] = cid >> 3;
        lc[j] = cid & 7;
        lso[j] = (uint32_t)(lrow[j] * 128 + ((lc[j] ^ (lrow[j] & 7)) * 16));
    }

    auto prefetch = [&](int k0, int st) {
        #pragma unroll
        for (int j = 0; j < 4; j++) {
            const __nv_bfloat16* ga = A + (size_t)(m0 + lrow[j]) * K3 + k0 + lc[j] * 8;
            const __nv_bfloat16* gb = B + (size_t)(n0 + lrow[j]) * K3 + k0 + lc[j] * 8;
            cpasync16(sb + SAo[st] + lso[j], ga);
            cpasync16(sb + SBo[st] + lso[j], gb);
        }
        asm volatile("cp.async.commit_group;" ::: "memory");
    };

    float acc[4][4][4];
    #pragma unroll
    for (int i = 0; i < 4; i++)
        #pragma unroll
        for (int j = 0; j < 4; j++)
            #pragma unroll
            for (int r = 0; r < 4; r++) acc[i][j][r] = 0.f;

    int rowA[4], rowB[4];
    #pragma unroll
    for (int mi = 0; mi < 4; mi++) rowA[mi] = wm * 64 + mi * 16 + (lane & 15);
    #pragma unroll
    for (int nj = 0; nj < 4; nj++) rowB[nj] = wn * 32 + nj * 8 + (lane & 7);
    int hiA = lane >> 4;
    int hiB = (lane >> 3) & 1;

    int nk = K3 >> 6;
    prefetch(0, 0);
    prefetch(64, 1);

    for (int t = 0; t < nk; t++) {
        asm volatile("cp.async.wait_group 1;" ::: "memory");
        __syncthreads();
        if (t + 2 < nk) prefetch((t + 2) * 64, (t + 2) % 3);
        else asm volatile("cp.async.commit_group;" ::: "memory");
        int cur = t % 3;
        #pragma unroll
        for (int ks = 0; ks < 4; ks++) {
            // load B fragments first (8 regs), then stream A fragments one at a time
            uint32_t bf[4][2];
            #pragma unroll
            for (int nj = 0; nj < 4; nj++) {
                uint32_t off = (uint32_t)(rowB[nj] * 128 + (((2 * ks + hiB) ^ (rowB[nj] & 7)) * 16));
                ldsm2(bf[nj], sb + SBo[cur] + off);
            }
            #pragma unroll
            for (int mi = 0; mi < 4; mi++) {
                uint32_t af[4];
                uint32_t off = (uint32_t)(rowA[mi] * 128 + (((2 * ks + hiA) ^ (rowA[mi] & 7)) * 16));
                ldsm4(af, sb + SAo[cur] + off);
                #pragma unroll
                for (int nj = 0; nj < 4; nj++)
                    mma16816(acc[mi][nj], af, bf[nj]);
            }
        }
    }
    __syncthreads();

    int rbase = m0 + wm * 64 + (lane >> 2);
    int cbase = n0 + wn * 32 + 2 * (lane & 3);
    #pragma unroll
    for (int mi = 0; mi < 4; mi++) {
        #pragma unroll
        for (int rh = 0; rh < 2; rh++) {
            int row = rbase + mi * 16 + rh * 8;
            float* crow = C + (size_t)row * sC;
            #pragma unroll
            for (int nj = 0; nj < 4; nj++) {
                #pragma unroll
                for (int cl = 0; cl < 2; cl++) {
                    int col = cbase + nj * 8 + cl;
                    if (col < N) {
                        float v = acc[mi][nj][rh * 2 + cl];
                        if (bias) v += bias[col];
                        if (act == 1) v = fmaxf(v, 0.f) + log1pf(__expf(-fabsf(v)));
                        crow[col] = v;
                    }
                }
            }
        }
    }
}

// ---------------- weights: fp32 -> [Bh|Bl|Bh] ----------------
__global__ void cvt_w3(const float* __restrict__ W, int N, int K, int Np, int Kp,
                       __nv_bfloat16* __restrict__ dst) {
    int idx = blockIdx.x * blockDim.x + threadIdx.x;
    if (idx >= Np * Kp) return;
    int k = idx % Kp, n = idx / Kp;
    float v = (n < N && k < K) ? W[(size_t)n * K + k] : 0.f;
    __nv_bfloat16 h, l;
    split_bf16(v, h, l);
    size_t base = (size_t)n * (3 * Kp);
    dst[base + k] = h;
    dst[base + Kp + k] = l;
    dst[base + 2 * Kp + k] = h;
}

// ---------------- dt slice: dbl[:, :25] -> [Ah|Ah|Al] Kp=64 ----------------
__global__ void cvt_dt(const float* __restrict__ dbl, __nv_bfloat16* __restrict__ dst) {
    int idx = blockIdx.x * blockDim.x + threadIdx.x;
    if (idx >= TOK * KP_DT) return;
    int k = idx % KP_DT, r = idx / KP_DT;
    float v = (k < DR) ? dbl[(size_t)r * XPO + k] : 0.f;
    __nv_bfloat16 h, l;
    split_bf16(v, h, l);
    size_t base = (size_t)r * (3 * KP_DT);
    dst[base + k] = h;
    dst[base + KP_DT + k] = h;
    dst[base + 2 * KP_DT + k] = l;
}

// ---------------- layernorm fused with split (Kp=448 layout) ----------------
__global__ void ln_split(const float* __restrict__ x, const float* __restrict__ g,
                         const float* __restrict__ beta, __nv_bfloat16* __restrict__ a3) {
    int t = blockIdx.x;
    const float* xr = x + (size_t)t * DM;
    float s = 0.f, s2 = 0.f;
    for (int i = threadIdx.x; i < DM; i += 128) {
        float v = xr[i]; s += v; s2 += v * v;
    }
    #pragma unroll
    for (int o = 16; o; o >>= 1) {
        s  += __shfl_down_sync(0xffffffffu, s,  o);
        s2 += __shfl_down_sync(0xffffffffu, s2, o);
    }
    __shared__ float sh[2][4];
    __shared__ float mu_s, rs_s;
    int w = threadIdx.x >> 5, ln = threadIdx.x & 31;
    if (ln == 0) { sh[0][w] = s; sh[1][w] = s2; }
    __syncthreads();
    if (threadIdx.x == 0) {
        float S  = sh[0][0] + sh[0][1] + sh[0][2] + sh[0][3];
        float S2 = sh[1][0] + sh[1][1] + sh[1][2] + sh[1][3];
        float mu = S / DM;
        float var = S2 / DM - mu * mu;
        mu_s = mu;
        rs_s = rsqrtf(var + 1e-5f);
    }
    __syncthreads();
    float mu = mu_s, rs = rs_s;
    __nv_bfloat16* row = a3 + (size_t)t * (3 * KP_IN);
    for (int i = threadIdx.x; i < KP_IN; i += 128) {
        float v = (i < DM) ? (xr[i] - mu) * rs * g[i] + beta[i] : 0.f;
        __nv_bfloat16 h, l;
        split_bf16(v, h, l);
        row[i] = h;
        row[KP_IN + i] = h;
        row[2 * KP_IN + i] = l;
    }
}

// ---------------- conv+SiLU fused with split (Kp=832) ----------------
__global__ void conv_silu_split(const float* __restrict__ xz, const float* __restrict__ cw,
                                const float* __restrict__ cb, float* __restrict__ xc,
                                __nv_bfloat16* __restrict__ a3) {
    int idx = blockIdx.x * blockDim.x + threadIdx.x;
    if (idx >= TOK * KP_XP) return;
    int d = idx % KP_XP;
    int r = idx / KP_XP;
    __nv_bfloat16* row = a3 + (size_t)r * (3 * KP_XP);
    if (d >= DI) {
        __nv_bfloat16 z = __float2bfloat16(0.f);
        row[d] = z; row[KP_XP + d] = z; row[2 * KP_XP + d] = z;
        return;
    }
    int l = r % SEQ;
    int b = r / SEQ;
    const float* base = xz + (size_t)(b * SEQ) * (2 * DI) + d;
    const float* w = cw + d * DC;
    float acc = cb[d];
    #pragma unroll
    for (int j = 0; j < DC; j++) {
        int ls = l - (DC - 1) + j;
        if (ls >= 0) acc += w[j] * base[(size_t)ls * (2 * DI)];
    }
    float v = acc / (1.f + __expf(-acc));
    xc[(size_t)r * DI + d] = v;
    __nv_bfloat16 h, lo;
    split_bf16(v, h, lo);
    row[d] = h; row[KP_XP + d] = h; row[2 * KP_XP + d] = lo;
}

// ---------------- selective scan, writes gated y directly as split (Kp=832) ----------------
__global__ void scan_split(const float* __restrict__ dt, const float* __restrict__ u,
                           const float* __restrict__ dbl, const float* __restrict__ xz,
                           const float* __restrict__ A_log, const float* __restrict__ Dp,
                           __nv_bfloat16* __restrict__ a3) {
    int idx = blockIdx.x * blockDim.x + threadIdx.x;
    if (idx >= BATCH * KP_XP) return;
    int d = idx % KP_XP;
    int b = idx / KP_XP;
    size_t tok0 = (size_t)b * SEQ;
    if (d >= DI) {
        __nv_bfloat16 z = __float2bfloat16(0.f);
        for (int l = 0; l < SEQ; l++) {
            __nv_bfloat16* row = a3 + (tok0 + l) * (3 * KP_XP);
            row[d] = z; row[KP_XP + d] = z; row[2 * KP_XP + d] = z;
        }
        return;
    }
    float Aa[DS];
    #pragma unroll
    for (int n = 0; n < DS; n++) Aa[n] = -__expf(A_log[d * DS + n]);
    float Dv = Dp[d];
    float h[DS];
    #pragma unroll
    for (int n = 0; n < DS; n++) h[n] = 0.f;
    for (int l = 0; l < SEQ; l++) {
        size_t t = tok0 + l;
        float dtv = dt[t * DI + d];
        float uv  = u [t * DI + d];
        const float* rb = dbl + t * XPO;
        float dtu = dtv * uv;
        float yy = 0.f;
        #pragma unroll
        for (int n = 0; n < DS; n++) {
            float e = __expf(dtv * Aa[n]);
            h[n] = e * h[n] + dtu * rb[DR + n];
            yy += h[n] * rb[DR + DS + n];
        }
        float zv = xz[t * (2 * DI) + DI + d];
        yy += uv * Dv;
        float v = yy * (zv / (1.f + __expf(-zv)));
        __nv_bfloat16 hh, ll;
        split_bf16(v, hh, ll);
        __nv_bfloat16* row = a3 + t * (3 * KP_XP);
        row[d] = hh; row[KP_XP + d] = hh; row[2 * KP_XP + d] = ll;
    }
}

// ---------------- classifier ----------------
__global__ void cls_kernel(const float* __restrict__ x, const float* __restrict__ w,
                           const float* __restrict__ bias, float* __restrict__ out) {
    int b = blockIdx.x;
    const float* xr = x + (size_t)b * FLAT;
    float a0 = 0.f, a1 = 0.f, a2 = 0.f;
    for (int i = threadIdx.x; i < FLAT; i += 256) {
        float v = xr[i];
        a0 += v * w[i];
        a1 += v * w[FLAT + i];
        a2 += v * w[2 * FLAT + i];
    }
    #pragma unroll
    for (int o = 16; o; o >>= 1) {
        a0 += __shfl_down_sync(0xffffffffu, a0, o);
        a1 += __shfl_down_sync(0xffffffffu, a1, o);
        a2 += __shfl_down_sync(0xffffffffu, a2, o);
    }
    __shared__ float sh[3][8];
    int wi = threadIdx.x >> 5, ln = threadIdx.x & 31;
    if (ln == 0) { sh[0][wi] = a0; sh[1][wi] = a1; sh[2][wi] = a2; }
    __syncthreads();
    if (threadIdx.x == 0) {
        float l0 = bias[0], l1 = bias[1], l2 = bias[2];
        for (int k = 0; k < 8; k++) { l0 += sh[0][k]; l1 += sh[1][k]; l2 += sh[2][k]; }
        float m = fmaxf(l0, fmaxf(l1, l2));
        float e0 = expf(l0 - m), e1 = expf(l1 - m), e2 = expf(l2 - m);
        float inv = 1.f / (e0 + e1 + e2);
        out[b * 3 + 0] = e0 * inv;
        out[b * 3 + 1] = e1 * inv;
        out[b * 3 + 2] = e2 * inv;
    }
}

// ---------------- host launch ----------------
#define MMA_SMEM 98304

extern "C" void kernel_launch(void* const* d_in, const int* in_sizes, int n_in,
                              void* d_out, int out_size) {
    const float* x_in   = (const float*)d_in[0];
    const float* ln_g   = (const float*)d_in[1];
    const float* ln_b   = (const float*)d_in[2];
    const float* inp_w  = (const float*)d_in[3];
    const float* conv_w = (const float*)d_in[4];
    const float* conv_b = (const float*)d_in[5];
    const float* xp_w   = (const float*)d_in[6];
    const float* dt_w   = (const float*)d_in[7];
    const float* dt_b   = (const float*)d_in[8];
    const float* A_log  = (const float*)d_in[9];
    const float* Dp     = (const float*)d_in[10];
    const float* out_w  = (const float*)d_in[11];
    const float* cls_w  = (const float*)d_in[12];
    const float* cls_b  = (const float*)d_in[13];
    float* out = (float*)d_out;

    float *p_xz, *p_xc, *p_dbl, *p_dt, *p_x;
    __nv_bfloat16 *p_a3, *p_b3;
    cudaGetSymbolAddress((void**)&p_xz,  g_xz);
    cudaGetSymbolAddress((void**)&p_xc,  g_xc);
    cudaGetSymbolAddress((void**)&p_dbl, g_dbl);
    cudaGetSymbolAddress((void**)&p_dt,  g_dt);
    cudaGetSymbolAddress((void**)&p_x,   g_x);
    cudaGetSymbolAddress((void**)&p_a3,  g_a3);
    cudaGetSymbolAddress((void**)&p_b3,  g_b3);

    cudaFuncSetAttribute(mma_gemm, cudaFuncAttributeMaxDynamicSharedMemorySize, MMA_SMEM);

    const int MB = TOK / 128;  // 290

    for (int i = 0; i < NB; i++) {
        const float* src = (i == 0) ? x_in : p_x;
        // layernorm + split (Kp=448)
        ln_split<<<TOK, 128>>>(src, ln_g + i * DM, ln_b + i * DM, p_a3);

        // ---- in_proj
        cvt_w3<<<(NP_IN * KP_IN + 255) / 256, 256>>>(inp_w + (size_t)i * 2 * DI * DM,
                                                     2 * DI, DM, NP_IN, KP_IN, p_b3);
        mma_gemm<<<dim3(MB, NP_IN / 128), 256, MMA_SMEM>>>(p_a3, p_b3, 3 * KP_IN,
                                                           p_xz, 2 * DI, 2 * DI, nullptr, 0);

        // conv + SiLU + split (Kp=832)
        conv_silu_split<<<(TOK * KP_XP + 255) / 256, 256>>>(
            p_xz, conv_w + (size_t)i * DI * DC, conv_b + (size_t)i * DI, p_xc, p_a3);

        // ---- x_proj
        cvt_w3<<<(NP_XP * KP_XP + 255) / 256, 256>>>(xp_w + (size_t)i * XPO * DI,
                                                     XPO, DI, NP_XP, KP_XP, p_b3);
        mma_gemm<<<dim3(MB, NP_XP / 128), 256, MMA_SMEM>>>(p_a3, p_b3, 3 * KP_XP,
                                                           p_dbl, XPO, XPO, nullptr, 0);

        // ---- dt_proj
        cvt_dt<<<(TOK * KP_DT + 255) / 256, 256>>>(p_dbl, p_a3);
        cvt_w3<<<(NP_DT * KP_DT + 255) / 256, 256>>>(dt_w + (size_t)i * DI * DR,
                                                     DI, DR, NP_DT, KP_DT, p_b3);
        mma_gemm<<<dim3(MB, NP_DT / 128), 256, MMA_SMEM>>>(p_a3, p_b3, 3 * KP_DT,
                                                           p_dt, DI, DI, dt_b + (size_t)i * DI, 1);

        // scan + gate + split (Kp=832)
        scan_split<<<(BATCH * KP_XP + 127) / 128, 128>>>(
            p_dt, p_xc, p_dbl, p_xz,
            A_log + (size_t)i * DI * DS, Dp + (size_t)i * DI, p_a3);

        // ---- out_proj
        cvt_w3<<<(NP_OUT * KP_OUT + 255) / 256, 256>>>(out_w + (size_t)i * DM * DI,
                                                       DM, DI, NP_OUT, KP_OUT, p_b3);
        mma_gemm<<<dim3(MB, NP_OUT / 128), 256, MMA_SMEM>>>(p_a3, p_b3, 3 * KP_OUT,
                                                            p_x, DM, DM, nullptr, 0);
    }

    cls_kernel<<<BATCH, 256>>>(p_x, cls_w, cls_b, out);
}